// round 10
// baseline (speedup 1.0000x reference)
#include <cuda_runtime.h>
#include <cuda_fp16.h>
#include <cstdint>
#include <math.h>

// ---------------- problem constants ----------------
#define N_NODES   50000
#define N_EDGES0  800000
#define N_EDGES   850000      // + self loops
#define F_IN      128
#define HID       64
#define HEADS     4
#define C1        256         // HEADS*HID
#define NG        64
#define SLOPE     0.2f

// ---------------- scratch (device globals) ----------------
__device__ __align__(16) __half g_W1h[F_IN * C1];
__device__ __align__(16) __half g_W2h[C1 * HID];
__device__ __align__(16) __half g_h1h[(size_t)N_NODES * C1];    // x @ W1 (fp16)
__device__ __align__(16) __half g_o1h[(size_t)N_NODES * C1];    // layer-1 out (fp16)
__device__ __align__(16) __half g_h2h[(size_t)N_NODES * HID];   // o1 @ W2 (fp16)
__device__ __align__(16) __half g_o2h[(size_t)N_NODES * HID];   // layer-2 out (fp16)

__device__ __align__(16) float g_ssrc1[N_NODES * HEADS];
__device__ __align__(16) float g_sdst1[N_NODES * HEADS];
__device__ float g_ssrc2[N_NODES];
__device__ float g_sdst2[N_NODES];

__device__ int g_deg[N_NODES];
__device__ int g_cursor[N_NODES];
__device__ int g_rowptr[N_NODES + 1];
__device__ int g_esrc[N_EDGES];
__device__ int g_goff[NG + 1];

// ---------------- fused fp32 -> fp16 convert of W1 and W2 (one launch) ----------------
__global__ void f2h2_kernel(const float* __restrict__ a, __half* __restrict__ oa, int na,
                            const float* __restrict__ b, __half* __restrict__ ob, int nb) {
    int i = (blockIdx.x * blockDim.x + threadIdx.x) * 4;
    const float* src;
    __half* dst;
    if (i < na) { src = a + i; dst = oa + i; }
    else {
        int j = i - na;
        if (j >= nb) return;
        src = b + j; dst = ob + j;
    }
    float4 v = *(const float4*)src;
    __half2 p0 = __floats2half2_rn(v.x, v.y);
    __half2 p1 = __floats2half2_rn(v.z, v.w);
    uint2 u;
    u.x = *(unsigned int*)&p0;
    u.y = *(unsigned int*)&p1;
    *(uint2*)dst = u;
}

// ---------------- CSR build ----------------
__global__ void hist_kernel(const int* __restrict__ ei) {
    int e = blockIdx.x * blockDim.x + threadIdx.x;
    if (e >= N_EDGES) return;
    int dst = (e < N_EDGES0) ? ei[N_EDGES0 + e] : (e - N_EDGES0);
    atomicAdd(&g_deg[dst], 1);
}

__global__ void scan_kernel() {
    __shared__ int warpsums[32];
    __shared__ int s_carry;
    int t = threadIdx.x;
    int lane = t & 31, warp = t >> 5;
    if (t == 0) s_carry = 0;
    __syncthreads();
    for (int base = 0; base < N_NODES; base += 4096) {
        int i0 = base + t * 4;
        int v[4];
        #pragma unroll
        for (int j = 0; j < 4; j++) v[j] = (i0 + j < N_NODES) ? g_deg[i0 + j] : 0;
        int s = v[0] + v[1] + v[2] + v[3];
        int x = s;
        #pragma unroll
        for (int o = 1; o < 32; o <<= 1) {
            int y = __shfl_up_sync(0xffffffffu, x, o);
            if (lane >= o) x += y;
        }
        if (lane == 31) warpsums[warp] = x;
        __syncthreads();
        if (warp == 0) {
            int w = warpsums[lane];
            #pragma unroll
            for (int o = 1; o < 32; o <<= 1) {
                int y = __shfl_up_sync(0xffffffffu, w, o);
                if (lane >= o) w += y;
            }
            warpsums[lane] = w;
        }
        __syncthreads();
        int excl = x - s + (warp ? warpsums[warp - 1] : 0) + s_carry;
        int run = excl;
        #pragma unroll
        for (int j = 0; j < 4; j++) {
            if (i0 + j < N_NODES) g_rowptr[i0 + j] = run;
            run += v[j];
        }
        int total = warpsums[31];
        __syncthreads();
        if (t == 0) s_carry += total;
        __syncthreads();
    }
    if (t == 0) g_rowptr[N_NODES] = s_carry;
}

__global__ void scatter_kernel(const int* __restrict__ ei) {
    int e = blockIdx.x * blockDim.x + threadIdx.x;
    if (e >= N_EDGES) return;
    int src, dst;
    if (e < N_EDGES0) { src = ei[e]; dst = ei[N_EDGES0 + e]; }
    else { src = e - N_EDGES0; dst = src; }
    int pos = g_rowptr[dst] + atomicAdd(&g_cursor[dst], 1);
    g_esrc[pos] = src;
}

// ---------------- fp16 HMMA GEMM + fused attention scores (register-pipelined) ----------------
// C_fp16[M,Nn] = A[M,K] @ B_fp16[K,Nn]; A fp32 (converted in staging) or fp16.
// BN == 64 == head width, so head = blockIdx.x.
#define ASTR 40   // half stride of As row (80B)
#define BSTR 72   // half stride of Bs row (144B)

__device__ __forceinline__ unsigned int smem_u32(const void* p) {
    return (unsigned int)__cvta_generic_to_shared(p);
}

__device__ __forceinline__ void ldsm_x4(unsigned int* r, unsigned int addr) {
    asm volatile("ldmatrix.sync.aligned.m8n8.x4.shared.b16 {%0,%1,%2,%3}, [%4];"
                 : "=r"(r[0]), "=r"(r[1]), "=r"(r[2]), "=r"(r[3]) : "r"(addr));
}

__device__ __forceinline__ void ldsm_x4_t(unsigned int* r, unsigned int addr) {
    asm volatile("ldmatrix.sync.aligned.m8n8.x4.trans.shared.b16 {%0,%1,%2,%3}, [%4];"
                 : "=r"(r[0]), "=r"(r[1]), "=r"(r[2]), "=r"(r[3]) : "r"(addr));
}

__device__ __forceinline__ void mma_f16(float* d, const unsigned int* a,
                                        unsigned int b0, unsigned int b1) {
    asm volatile(
        "mma.sync.aligned.m16n8k16.row.col.f32.f16.f16.f32 "
        "{%0,%1,%2,%3}, {%4,%5,%6,%7}, {%8,%9}, {%0,%1,%2,%3};"
        : "+f"(d[0]), "+f"(d[1]), "+f"(d[2]), "+f"(d[3])
        : "r"(a[0]), "r"(a[1]), "r"(a[2]), "r"(a[3]), "r"(b0), "r"(b1));
}

template <bool AF32>
__global__ void __launch_bounds__(256) gemm_gat_kernel(
    const void* __restrict__ Av, const __half* __restrict__ B, __half* __restrict__ C,
    int M, int Nn, int K,
    const float* __restrict__ asrc, const float* __restrict__ adst,
    float* __restrict__ ssrc, float* __restrict__ sdst, int heads)
{
    __shared__ __half As[128 * ASTR];
    __shared__ __half Bs[32 * BSTR];
    __shared__ float sSm[2][128];
    __shared__ float sDm[2][128];

    int t = threadIdx.x;
    int lane = t & 31, w = t >> 5;
    int wm = w >> 1, wn = w & 1;
    int bm = blockIdx.y * 128, bn = blockIdx.x * 64;
    int head = blockIdx.x;

    // staging coordinates
    int arow = t >> 1, ach = t & 1;
    int gm = bm + arow;
    int brow = t >> 3, bch = t & 7;

    float acc[2][4][4] = {};

    // prefetch registers
    float4 fa[4];
    uint4 ha0 = make_uint4(0, 0, 0, 0), ha1 = ha0;
    uint4 hb;

    // ---- prologue: load tile 0 ----
    if (AF32) {
        const float* A = (const float*)Av;
        if (gm < M) {
            const float4* src = (const float4*)(A + (size_t)gm * K + ach * 16);
            fa[0] = src[0]; fa[1] = src[1]; fa[2] = src[2]; fa[3] = src[3];
        } else {
            fa[0] = fa[1] = fa[2] = fa[3] = make_float4(0.f, 0.f, 0.f, 0.f);
        }
    } else {
        const __half* A = (const __half*)Av;
        if (gm < M) {
            const uint4* src = (const uint4*)(A + (size_t)gm * K + ach * 16);
            ha0 = src[0]; ha1 = src[1];
        }
    }
    hb = *(const uint4*)(B + (size_t)brow * Nn + bn + bch * 8);

    for (int kk = 0; kk < K; kk += 32) {
        // ---- STS current tile ----
        {
            uint4 v0, v1;
            if (AF32) {
                __half2 h0 = __floats2half2_rn(fa[0].x, fa[0].y);
                __half2 h1 = __floats2half2_rn(fa[0].z, fa[0].w);
                __half2 h2 = __floats2half2_rn(fa[1].x, fa[1].y);
                __half2 h3 = __floats2half2_rn(fa[1].z, fa[1].w);
                __half2 h4 = __floats2half2_rn(fa[2].x, fa[2].y);
                __half2 h5 = __floats2half2_rn(fa[2].z, fa[2].w);
                __half2 h6 = __floats2half2_rn(fa[3].x, fa[3].y);
                __half2 h7 = __floats2half2_rn(fa[3].z, fa[3].w);
                v0.x = *(unsigned int*)&h0; v0.y = *(unsigned int*)&h1;
                v0.z = *(unsigned int*)&h2; v0.w = *(unsigned int*)&h3;
                v1.x = *(unsigned int*)&h4; v1.y = *(unsigned int*)&h5;
                v1.z = *(unsigned int*)&h6; v1.w = *(unsigned int*)&h7;
            } else {
                v0 = ha0; v1 = ha1;
            }
            *(uint4*)&As[arow * ASTR + ach * 16] = v0;
            *(uint4*)&As[arow * ASTR + ach * 16 + 8] = v1;
            *(uint4*)&Bs[brow * BSTR + bch * 8] = hb;
        }
        __syncthreads();

        // ---- prefetch next tile into registers (overlaps MMA below) ----
        int kn = kk + 32;
        if (kn < K) {
            if (AF32) {
                const float* A = (const float*)Av;
                if (gm < M) {
                    const float4* src = (const float4*)(A + (size_t)gm * K + kn + ach * 16);
                    fa[0] = src[0]; fa[1] = src[1]; fa[2] = src[2]; fa[3] = src[3];
                }
            } else {
                const __half* A = (const __half*)Av;
                if (gm < M) {
                    const uint4* src = (const uint4*)(A + (size_t)gm * K + kn + ach * 16);
                    ha0 = src[0]; ha1 = src[1];
                }
            }
            hb = *(const uint4*)(B + (size_t)(kn + brow) * Nn + bn + bch * 8);
        }

        // ---- compute ----
        #pragma unroll
        for (int ks = 0; ks < 2; ks++) {
            unsigned int a[2][4], b[2][4];
            #pragma unroll
            for (int mt = 0; mt < 2; mt++) {
                unsigned int addr = smem_u32(
                    &As[(wm * 32 + mt * 16 + (lane & 15)) * ASTR + ks * 16 + (lane >> 4) * 8]);
                ldsm_x4(a[mt], addr);
            }
            #pragma unroll
            for (int np = 0; np < 2; np++) {
                unsigned int addr = smem_u32(
                    &Bs[(ks * 16 + (lane & 15)) * BSTR + wn * 32 + np * 16 + (lane >> 4) * 8]);
                ldsm_x4_t(b[np], addr);
            }
            #pragma unroll
            for (int mt = 0; mt < 2; mt++)
                #pragma unroll
                for (int nt = 0; nt < 4; nt++)
                    mma_f16(acc[mt][nt], a[mt], b[nt >> 1][(nt & 1) * 2], b[nt >> 1][(nt & 1) * 2 + 1]);
        }
        __syncthreads();
    }

    // ---- fused attention scores ----
    {
        float av[4][2], dv[4][2];
        #pragma unroll
        for (int nt = 0; nt < 4; nt++) {
            int c = head * 64 + wn * 32 + nt * 8 + (lane & 3) * 2;
            av[nt][0] = asrc[c]; av[nt][1] = asrc[c + 1];
            dv[nt][0] = adst[c]; dv[nt][1] = adst[c + 1];
        }
        #pragma unroll
        for (int mt = 0; mt < 2; mt++) {
            #pragma unroll
            for (int hf = 0; hf < 2; hf++) {
                float sS = 0.f, sD = 0.f;
                #pragma unroll
                for (int nt = 0; nt < 4; nt++) {
                    sS += acc[mt][nt][hf * 2 + 0] * av[nt][0]
                        + acc[mt][nt][hf * 2 + 1] * av[nt][1];
                    sD += acc[mt][nt][hf * 2 + 0] * dv[nt][0]
                        + acc[mt][nt][hf * 2 + 1] * dv[nt][1];
                }
                sS += __shfl_xor_sync(0xffffffffu, sS, 1);
                sS += __shfl_xor_sync(0xffffffffu, sS, 2);
                sD += __shfl_xor_sync(0xffffffffu, sD, 1);
                sD += __shfl_xor_sync(0xffffffffu, sD, 2);
                if ((lane & 3) == 0) {
                    int rowl = wm * 32 + mt * 16 + hf * 8 + (lane >> 2);
                    sSm[wn][rowl] = sS;
                    sDm[wn][rowl] = sD;
                }
            }
        }
        __syncthreads();
        if (t < 128) {
            int gmr = bm + t;
            if (gmr < M) {
                ssrc[gmr * heads + head] = sSm[0][t] + sSm[1][t];
                sdst[gmr * heads + head] = sDm[0][t] + sDm[1][t];
            }
        }
    }

    // ---- C stores ----
    #pragma unroll
    for (int mt = 0; mt < 2; mt++) {
        int r0 = bm + wm * 32 + mt * 16 + (lane >> 2);
        #pragma unroll
        for (int nt = 0; nt < 4; nt++) {
            int c0 = bn + wn * 32 + nt * 8 + (lane & 3) * 2;
            if (r0 < M)
                *(__half2*)(C + (size_t)r0 * Nn + c0) =
                    __floats2half2_rn(acc[mt][nt][0], acc[mt][nt][1]);
            if (r0 + 8 < M)
                *(__half2*)(C + (size_t)(r0 + 8) * Nn + c0) =
                    __floats2half2_rn(acc[mt][nt][2], acc[mt][nt][3]);
        }
    }
}

// ---------------- helpers ----------------
__device__ __forceinline__ float lrelu_exp(float s) {
    s = s > 0.f ? s : SLOPE * s;
    return __expf(s);
}

__device__ __forceinline__ void acc8(float* acc, float w, const uint4& v) {
    float2 f0 = __half22float2(*(__half2*)&v.x);
    float2 f1 = __half22float2(*(__half2*)&v.y);
    float2 f2 = __half22float2(*(__half2*)&v.z);
    float2 f3 = __half22float2(*(__half2*)&v.w);
    acc[0] += w * f0.x; acc[1] += w * f0.y;
    acc[2] += w * f1.x; acc[3] += w * f1.y;
    acc[4] += w * f2.x; acc[5] += w * f2.y;
    acc[6] += w * f3.x; acc[7] += w * f3.y;
}

// ---------------- aggregation layer 1: warp per node ----------------
__global__ void __launch_bounds__(256) aggregate1_kernel(const float* __restrict__ b1) {
    int n = (blockIdx.x * blockDim.x + threadIdx.x) >> 5;
    if (n >= N_NODES) return;
    int l = threadIdx.x & 31;
    int h = l >> 3;
    int r0 = g_rowptr[n], r1 = g_rowptr[n + 1];
    float dvh = g_sdst1[n * 4 + h];

    float acc[8] = {};
    float den = 0.f;
    const __half* hb = g_h1h + l * 8;

    int e = r0;
    for (; e + 3 < r1; e += 4) {
        int s0 = g_esrc[e], s1 = g_esrc[e + 1], s2 = g_esrc[e + 2], s3 = g_esrc[e + 3];
        float w0 = lrelu_exp(g_ssrc1[s0 * 4 + h] + dvh);
        float w1 = lrelu_exp(g_ssrc1[s1 * 4 + h] + dvh);
        float w2 = lrelu_exp(g_ssrc1[s2 * 4 + h] + dvh);
        float w3 = lrelu_exp(g_ssrc1[s3 * 4 + h] + dvh);
        uint4 v0 = *(const uint4*)(hb + (size_t)s0 * C1);
        uint4 v1 = *(const uint4*)(hb + (size_t)s1 * C1);
        uint4 v2 = *(const uint4*)(hb + (size_t)s2 * C1);
        uint4 v3 = *(const uint4*)(hb + (size_t)s3 * C1);
        acc8(acc, w0, v0); acc8(acc, w1, v1);
        acc8(acc, w2, v2); acc8(acc, w3, v3);
        den += (w0 + w1) + (w2 + w3);
    }
    for (; e < r1; e++) {
        int s0 = g_esrc[e];
        float w0 = lrelu_exp(g_ssrc1[s0 * 4 + h] + dvh);
        uint4 v0 = *(const uint4*)(hb + (size_t)s0 * C1);
        acc8(acc, w0, v0);
        den += w0;
    }

    float inv = 1.f / (den + 1e-16f);
    float4 bb0 = *(const float4*)(b1 + l * 8);
    float4 bb1 = *(const float4*)(b1 + l * 8 + 4);
    float o[8];
    o[0] = acc[0] * inv + bb0.x; o[1] = acc[1] * inv + bb0.y;
    o[2] = acc[2] * inv + bb0.z; o[3] = acc[3] * inv + bb0.w;
    o[4] = acc[4] * inv + bb1.x; o[5] = acc[5] * inv + bb1.y;
    o[6] = acc[6] * inv + bb1.z; o[7] = acc[7] * inv + bb1.w;
    #pragma unroll
    for (int j = 0; j < 8; j++) o[j] = o[j] > 0.f ? o[j] : expm1f(o[j]);
    __half2 p0 = __floats2half2_rn(o[0], o[1]);
    __half2 p1 = __floats2half2_rn(o[2], o[3]);
    __half2 p2 = __floats2half2_rn(o[4], o[5]);
    __half2 p3 = __floats2half2_rn(o[6], o[7]);
    uint4 u;
    u.x = *(unsigned int*)&p0; u.y = *(unsigned int*)&p1;
    u.z = *(unsigned int*)&p2; u.w = *(unsigned int*)&p3;
    *(uint4*)(g_o1h + (size_t)n * C1 + l * 8) = u;
}

// ---------------- aggregation layer 2: warp per node (fp16 out) ----------------
__global__ void __launch_bounds__(256) aggregate2_kernel(const float* __restrict__ b2) {
    int n = (blockIdx.x * blockDim.x + threadIdx.x) >> 5;
    if (n >= N_NODES) return;
    int l = threadIdx.x & 31;
    int r0 = g_rowptr[n], r1 = g_rowptr[n + 1];
    float sd = g_sdst2[n];

    float a0 = 0.f, a1 = 0.f;
    float den = 0.f;
    const __half* hb = g_h2h + l * 2;

    int e = r0;
    for (; e + 3 < r1; e += 4) {
        int s0 = g_esrc[e], s1 = g_esrc[e + 1], s2 = g_esrc[e + 2], s3 = g_esrc[e + 3];
        float w0 = lrelu_exp(g_ssrc2[s0] + sd);
        float w1 = lrelu_exp(g_ssrc2[s1] + sd);
        float w2 = lrelu_exp(g_ssrc2[s2] + sd);
        float w3 = lrelu_exp(g_ssrc2[s3] + sd);
        __half2 v0 = *(const __half2*)(hb + (size_t)s0 * HID);
        __half2 v1 = *(const __half2*)(hb + (size_t)s1 * HID);
        __half2 v2 = *(const __half2*)(hb + (size_t)s2 * HID);
        __half2 v3 = *(const __half2*)(hb + (size_t)s3 * HID);
        float2 f0 = __half22float2(v0), f1 = __half22float2(v1);
        float2 f2 = __half22float2(v2), f3 = __half22float2(v3);
        a0 += w0 * f0.x + w1 * f1.x + w2 * f2.x + w3 * f3.x;
        a1 += w0 * f0.y + w1 * f1.y + w2 * f2.y + w3 * f3.y;
        den += (w0 + w1) + (w2 + w3);
    }
    for (; e < r1; e++) {
        int s0 = g_esrc[e];
        float w0 = lrelu_exp(g_ssrc2[s0] + sd);
        float2 f0 = __half22float2(*(const __half2*)(hb + (size_t)s0 * HID));
        a0 += w0 * f0.x; a1 += w0 * f0.y;
        den += w0;
    }

    float inv = 1.f / (den + 1e-16f);
    float o0 = a0 * inv + b2[l * 2];
    float o1 = a1 * inv + b2[l * 2 + 1];
    o0 = o0 > 0.f ? o0 : expm1f(o0);
    o1 = o1 > 0.f ? o1 : expm1f(o1);
    *(__half2*)(g_o2h + (size_t)n * HID + l * 2) = __floats2half2_rn(o0, o1);
}

// ---------------- graph offsets ----------------
__global__ void graph_offsets_kernel(const int* __restrict__ batch) {
    int g = blockIdx.x * blockDim.x + threadIdx.x;
    if (g > NG) return;
    if (g == NG) { g_goff[NG] = N_NODES; return; }
    int lo = 0, hi = N_NODES;
    while (lo < hi) {
        int mid = (lo + hi) >> 1;
        if (batch[mid] < g) lo = mid + 1; else hi = mid;
    }
    g_goff[g] = lo;
}

// ---------------- pool + fc + log_softmax (fp16 in) ----------------
__global__ void __launch_bounds__(256) pool_fc_kernel(const float* __restrict__ fcw,
                                                      const float* __restrict__ fcb,
                                                      float* __restrict__ out) {
    int g = blockIdx.x;
    int t = threadIdx.x;
    int c2 = t & 31, rep = t >> 5;   // 32 channel-pairs x 8 reps
    int s = g_goff[g], e = g_goff[g + 1];
    float sx = 0.f, sy = 0.f;
    for (int i = s + rep; i < e; i += 8) {
        float2 f = __half22float2(*(const __half2*)(g_o2h + (size_t)i * HID + c2 * 2));
        sx += f.x; sy += f.y;
    }
    __shared__ float2 red[256];
    red[t] = make_float2(sx, sy);
    __syncthreads();
    if (t < 32) {
        float2 tot = make_float2(0.f, 0.f);
        #pragma unroll
        for (int r = 0; r < 8; r++) {
            float2 v = red[r * 32 + t];
            tot.x += v.x; tot.y += v.y;
        }
        float cnt = (float)max(e - s, 1);
        red[t] = make_float2(tot.x / cnt, tot.y / cnt);
    }
    __syncthreads();
    if (t < 2) {
        float l = fcb[t];
        for (int c = 0; c < 32; c++) {
            float2 p = red[c];
            l += p.x * fcw[(c * 2) * 2 + t] + p.y * fcw[(c * 2 + 1) * 2 + t];
        }
        red[64 + t].x = l;
    }
    __syncthreads();
    if (t == 0) {
        float l0 = red[64].x, l1 = red[65].x;
        float m = fmaxf(l0, l1);
        float lse = m + logf(__expf(l0 - m) + __expf(l1 - m));
        out[g * 2 + 0] = l0 - lse;
        out[g * 2 + 1] = l1 - lse;
    }
}

// ---------------- launch ----------------
extern "C" void kernel_launch(void* const* d_in, const int* in_sizes, int n_in,
                              void* d_out, int out_size) {
    const float* x    = (const float*)d_in[0];
    const int*   ei   = (const int*)d_in[1];
    const int*   bat  = (const int*)d_in[2];
    const float* W1   = (const float*)d_in[3];
    const float* as1  = (const float*)d_in[4];
    const float* ad1  = (const float*)d_in[5];
    const float* b1   = (const float*)d_in[6];
    const float* W2   = (const float*)d_in[7];
    const float* as2  = (const float*)d_in[8];
    const float* ad2  = (const float*)d_in[9];
    const float* b2   = (const float*)d_in[10];
    const float* fcw  = (const float*)d_in[11];
    const float* fcb  = (const float*)d_in[12];
    float* out = (float*)d_out;

    __half* w1hp; cudaGetSymbolAddress((void**)&w1hp, g_W1h);
    __half* w2hp; cudaGetSymbolAddress((void**)&w2hp, g_W2h);
    __half* h1p;  cudaGetSymbolAddress((void**)&h1p,  g_h1h);
    __half* o1p;  cudaGetSymbolAddress((void**)&o1p,  g_o1h);
    __half* h2p;  cudaGetSymbolAddress((void**)&h2p,  g_h2h);
    float* s1p;   cudaGetSymbolAddress((void**)&s1p,  g_ssrc1);
    float* d1p;   cudaGetSymbolAddress((void**)&d1p,  g_sdst1);
    float* s2p;   cudaGetSymbolAddress((void**)&s2p,  g_ssrc2);
    float* d2p;   cudaGetSymbolAddress((void**)&d2p,  g_sdst2);
    int* degp;    cudaGetSymbolAddress((void**)&degp, g_deg);
    int* curp;    cudaGetSymbolAddress((void**)&curp, g_cursor);

    // side stream + events for fork/join inside graph capture
    cudaStream_t side;
    cudaStreamCreateWithFlags(&side, cudaStreamNonBlocking);
    cudaEvent_t evF, evJ;
    cudaEventCreateWithFlags(&evF, cudaEventDisableTiming);
    cudaEventCreateWithFlags(&evJ, cudaEventDisableTiming);

    // fork: CSR build + graph offsets on side stream
    cudaEventRecord(evF, 0);
    cudaStreamWaitEvent(side, evF, 0);
    cudaMemsetAsync(degp, 0, N_NODES * sizeof(int), side);
    cudaMemsetAsync(curp, 0, N_NODES * sizeof(int), side);
    graph_offsets_kernel<<<1, 128, 0, side>>>(bat);
    hist_kernel<<<(N_EDGES + 255) / 256, 256, 0, side>>>(ei);
    scan_kernel<<<1, 1024, 0, side>>>();
    scatter_kernel<<<(N_EDGES + 255) / 256, 256, 0, side>>>(ei);
    cudaEventRecord(evJ, side);

    // main: weight converts (one launch) + gemm1 (scores fused)
    int nW = F_IN * C1 + C1 * HID;
    f2h2_kernel<<<(nW / 4 + 255) / 256, 256>>>(W1, w1hp, F_IN * C1, W2, w2hp, C1 * HID);

    dim3 g1(C1 / 64, (N_NODES + 127) / 128);
    gemm_gat_kernel<true><<<g1, 256>>>(x, w1hp, h1p, N_NODES, C1, F_IN,
                                       as1, ad1, s1p, d1p, HEADS);

    // join: aggregate1 needs CSR + scores
    cudaStreamWaitEvent(0, evJ, 0);
    aggregate1_kernel<<<(N_NODES * 32 + 255) / 256, 256>>>(b1);

    // layer 2 (scores fused)
    dim3 g2(HID / 64, (N_NODES + 127) / 128);
    gemm_gat_kernel<false><<<g2, 256>>>(o1p, w2hp, h2p, N_NODES, HID, C1,
                                        as2, ad2, s2p, d2p, 1);
    aggregate2_kernel<<<(N_NODES * 32 + 255) / 256, 256>>>(b2);

    // pool + classifier
    pool_fc_kernel<<<NG, 256>>>(fcw, fcb, out);
}

// round 11
// speedup vs baseline: 1.0954x; 1.0954x over previous
#include <cuda_runtime.h>
#include <cuda_fp16.h>
#include <cstdint>
#include <math.h>

// ---------------- problem constants ----------------
#define N_NODES   50000
#define N_EDGES0  800000
#define N_EDGES   850000      // + self loops
#define F_IN      128
#define HID       64
#define HEADS     4
#define C1        256         // HEADS*HID
#define NG        64
#define SLOPE     0.2f

// ---------------- scratch (device globals) ----------------
__device__ __align__(16) __half g_W1h[F_IN * C1];
__device__ __align__(16) __half g_W2h[C1 * HID];
__device__ __align__(16) __half g_h1h[(size_t)N_NODES * C1];    // x @ W1 (fp16)
__device__ __align__(16) __half g_o1h[(size_t)N_NODES * C1];    // layer-1 out (fp16)
__device__ __align__(16) __half g_h2h[(size_t)N_NODES * HID];   // o1 @ W2 (fp16)
__device__ __align__(16) __half g_o2h[(size_t)N_NODES * HID];   // layer-2 out (fp16)

__device__ __align__(16) float g_ssrc1[N_NODES * HEADS];
__device__ __align__(16) float g_sdst1[N_NODES * HEADS];
__device__ float g_ssrc2[N_NODES];
__device__ float g_sdst2[N_NODES];

__device__ int g_deg[N_NODES];
__device__ int g_cursor[N_NODES];
__device__ int g_rowptr[N_NODES + 1];
__device__ int g_esrc[N_EDGES];
__device__ int g_goff[NG + 1];

// ---------------- fused fp32 -> fp16 convert of W1 and W2 (one launch) ----------------
__global__ void f2h2_kernel(const float* __restrict__ a, __half* __restrict__ oa, int na,
                            const float* __restrict__ b, __half* __restrict__ ob, int nb) {
    int i = (blockIdx.x * blockDim.x + threadIdx.x) * 4;
    const float* src;
    __half* dst;
    if (i < na) { src = a + i; dst = oa + i; }
    else {
        int j = i - na;
        if (j >= nb) return;
        src = b + j; dst = ob + j;
    }
    float4 v = *(const float4*)src;
    __half2 p0 = __floats2half2_rn(v.x, v.y);
    __half2 p1 = __floats2half2_rn(v.z, v.w);
    uint2 u;
    u.x = *(unsigned int*)&p0;
    u.y = *(unsigned int*)&p1;
    *(uint2*)dst = u;
}

// ---------------- CSR build ----------------
__global__ void hist_kernel(const int* __restrict__ ei) {
    int e = blockIdx.x * blockDim.x + threadIdx.x;
    if (e >= N_EDGES) return;
    int dst = (e < N_EDGES0) ? ei[N_EDGES0 + e] : (e - N_EDGES0);
    atomicAdd(&g_deg[dst], 1);
}

__global__ void scan_kernel() {
    __shared__ int warpsums[32];
    __shared__ int s_carry;
    int t = threadIdx.x;
    int lane = t & 31, warp = t >> 5;
    if (t == 0) s_carry = 0;
    __syncthreads();
    for (int base = 0; base < N_NODES; base += 4096) {
        int i0 = base + t * 4;
        int v[4];
        #pragma unroll
        for (int j = 0; j < 4; j++) v[j] = (i0 + j < N_NODES) ? g_deg[i0 + j] : 0;
        int s = v[0] + v[1] + v[2] + v[3];
        int x = s;
        #pragma unroll
        for (int o = 1; o < 32; o <<= 1) {
            int y = __shfl_up_sync(0xffffffffu, x, o);
            if (lane >= o) x += y;
        }
        if (lane == 31) warpsums[warp] = x;
        __syncthreads();
        if (warp == 0) {
            int w = warpsums[lane];
            #pragma unroll
            for (int o = 1; o < 32; o <<= 1) {
                int y = __shfl_up_sync(0xffffffffu, w, o);
                if (lane >= o) w += y;
            }
            warpsums[lane] = w;
        }
        __syncthreads();
        int excl = x - s + (warp ? warpsums[warp - 1] : 0) + s_carry;
        int run = excl;
        #pragma unroll
        for (int j = 0; j < 4; j++) {
            if (i0 + j < N_NODES) g_rowptr[i0 + j] = run;
            run += v[j];
        }
        int total = warpsums[31];
        __syncthreads();
        if (t == 0) s_carry += total;
        __syncthreads();
    }
    if (t == 0) g_rowptr[N_NODES] = s_carry;
}

__global__ void scatter_kernel(const int* __restrict__ ei) {
    int e = blockIdx.x * blockDim.x + threadIdx.x;
    if (e >= N_EDGES) return;
    int src, dst;
    if (e < N_EDGES0) { src = ei[e]; dst = ei[N_EDGES0 + e]; }
    else { src = e - N_EDGES0; dst = src; }
    int pos = g_rowptr[dst] + atomicAdd(&g_cursor[dst], 1);
    g_esrc[pos] = src;
}

// ---------------- fp16 HMMA GEMM + fused attention scores ----------------
// C_fp16[M,Nn] = A[M,K] @ B_fp16[K,Nn]; A fp32 (converted in staging) or fp16.
// BN == 64 == head width, so head = blockIdx.x.
#define ASTR 40   // half stride of As row (80B)
#define BSTR 72   // half stride of Bs row (144B)

__device__ __forceinline__ unsigned int smem_u32(const void* p) {
    return (unsigned int)__cvta_generic_to_shared(p);
}

__device__ __forceinline__ void ldsm_x4(unsigned int* r, unsigned int addr) {
    asm volatile("ldmatrix.sync.aligned.m8n8.x4.shared.b16 {%0,%1,%2,%3}, [%4];"
                 : "=r"(r[0]), "=r"(r[1]), "=r"(r[2]), "=r"(r[3]) : "r"(addr));
}

__device__ __forceinline__ void ldsm_x4_t(unsigned int* r, unsigned int addr) {
    asm volatile("ldmatrix.sync.aligned.m8n8.x4.trans.shared.b16 {%0,%1,%2,%3}, [%4];"
                 : "=r"(r[0]), "=r"(r[1]), "=r"(r[2]), "=r"(r[3]) : "r"(addr));
}

__device__ __forceinline__ void mma_f16(float* d, const unsigned int* a,
                                        unsigned int b0, unsigned int b1) {
    asm volatile(
        "mma.sync.aligned.m16n8k16.row.col.f32.f16.f16.f32 "
        "{%0,%1,%2,%3}, {%4,%5,%6,%7}, {%8,%9}, {%0,%1,%2,%3};"
        : "+f"(d[0]), "+f"(d[1]), "+f"(d[2]), "+f"(d[3])
        : "r"(a[0]), "r"(a[1]), "r"(a[2]), "r"(a[3]), "r"(b0), "r"(b1));
}

template <bool AF32>
__global__ void __launch_bounds__(256) gemm_gat_kernel(
    const void* __restrict__ Av, const __half* __restrict__ B, __half* __restrict__ C,
    int M, int Nn, int K,
    const float* __restrict__ asrc, const float* __restrict__ adst,
    float* __restrict__ ssrc, float* __restrict__ sdst, int heads)
{
    __shared__ __half As[128 * ASTR];
    __shared__ __half Bs[32 * BSTR];
    __shared__ float sSm[2][128];
    __shared__ float sDm[2][128];

    int t = threadIdx.x;
    int lane = t & 31, w = t >> 5;
    int wm = w >> 1, wn = w & 1;
    int bm = blockIdx.y * 128, bn = blockIdx.x * 64;
    int head = blockIdx.x;

    float acc[2][4][4] = {};

    for (int kk = 0; kk < K; kk += 32) {
        // stage A
        {
            int row = t >> 1, ch = t & 1;
            int gm = bm + row;
            uint4 v0 = make_uint4(0, 0, 0, 0), v1 = v0;
            if (AF32) {
                const float* A = (const float*)Av;
                if (gm < M) {
                    const float4* src = (const float4*)(A + (size_t)gm * K + kk + ch * 16);
                    float4 f0 = src[0], f1 = src[1], f2 = src[2], f3 = src[3];
                    __half2 h0 = __floats2half2_rn(f0.x, f0.y);
                    __half2 h1 = __floats2half2_rn(f0.z, f0.w);
                    __half2 h2 = __floats2half2_rn(f1.x, f1.y);
                    __half2 h3 = __floats2half2_rn(f1.z, f1.w);
                    __half2 h4 = __floats2half2_rn(f2.x, f2.y);
                    __half2 h5 = __floats2half2_rn(f2.z, f2.w);
                    __half2 h6 = __floats2half2_rn(f3.x, f3.y);
                    __half2 h7 = __floats2half2_rn(f3.z, f3.w);
                    v0.x = *(unsigned int*)&h0; v0.y = *(unsigned int*)&h1;
                    v0.z = *(unsigned int*)&h2; v0.w = *(unsigned int*)&h3;
                    v1.x = *(unsigned int*)&h4; v1.y = *(unsigned int*)&h5;
                    v1.z = *(unsigned int*)&h6; v1.w = *(unsigned int*)&h7;
                }
            } else {
                const __half* A = (const __half*)Av;
                if (gm < M) {
                    const uint4* src = (const uint4*)(A + (size_t)gm * K + kk + ch * 16);
                    v0 = src[0]; v1 = src[1];
                }
            }
            *(uint4*)&As[row * ASTR + ch * 16] = v0;
            *(uint4*)&As[row * ASTR + ch * 16 + 8] = v1;
        }
        // stage B
        {
            int row = t >> 3, ch = t & 7;
            uint4 v = *(const uint4*)(B + (size_t)(kk + row) * Nn + bn + ch * 8);
            *(uint4*)&Bs[row * BSTR + ch * 8] = v;
        }
        __syncthreads();
        #pragma unroll
        for (int ks = 0; ks < 2; ks++) {
            unsigned int a[2][4], b[2][4];
            #pragma unroll
            for (int mt = 0; mt < 2; mt++) {
                unsigned int addr = smem_u32(
                    &As[(wm * 32 + mt * 16 + (lane & 15)) * ASTR + ks * 16 + (lane >> 4) * 8]);
                ldsm_x4(a[mt], addr);
            }
            #pragma unroll
            for (int np = 0; np < 2; np++) {
                unsigned int addr = smem_u32(
                    &Bs[(ks * 16 + (lane & 15)) * BSTR + wn * 32 + np * 16 + (lane >> 4) * 8]);
                ldsm_x4_t(b[np], addr);
            }
            #pragma unroll
            for (int mt = 0; mt < 2; mt++)
                #pragma unroll
                for (int nt = 0; nt < 4; nt++)
                    mma_f16(acc[mt][nt], a[mt], b[nt >> 1][(nt & 1) * 2], b[nt >> 1][(nt & 1) * 2 + 1]);
        }
        __syncthreads();
    }

    // ---- fused attention scores ----
    {
        float av[4][2], dv[4][2];
        #pragma unroll
        for (int nt = 0; nt < 4; nt++) {
            int c = head * 64 + wn * 32 + nt * 8 + (lane & 3) * 2;
            av[nt][0] = asrc[c]; av[nt][1] = asrc[c + 1];
            dv[nt][0] = adst[c]; dv[nt][1] = adst[c + 1];
        }
        #pragma unroll
        for (int mt = 0; mt < 2; mt++) {
            #pragma unroll
            for (int hf = 0; hf < 2; hf++) {
                float sS = 0.f, sD = 0.f;
                #pragma unroll
                for (int nt = 0; nt < 4; nt++) {
                    sS += acc[mt][nt][hf * 2 + 0] * av[nt][0]
                        + acc[mt][nt][hf * 2 + 1] * av[nt][1];
                    sD += acc[mt][nt][hf * 2 + 0] * dv[nt][0]
                        + acc[mt][nt][hf * 2 + 1] * dv[nt][1];
                }
                sS += __shfl_xor_sync(0xffffffffu, sS, 1);
                sS += __shfl_xor_sync(0xffffffffu, sS, 2);
                sD += __shfl_xor_sync(0xffffffffu, sD, 1);
                sD += __shfl_xor_sync(0xffffffffu, sD, 2);
                if ((lane & 3) == 0) {
                    int rowl = wm * 32 + mt * 16 + hf * 8 + (lane >> 2);
                    sSm[wn][rowl] = sS;
                    sDm[wn][rowl] = sD;
                }
            }
        }
        __syncthreads();
        if (t < 128) {
            int gm = bm + t;
            if (gm < M) {
                ssrc[gm * heads + head] = sSm[0][t] + sSm[1][t];
                sdst[gm * heads + head] = sDm[0][t] + sDm[1][t];
            }
        }
    }

    // ---- C stores ----
    #pragma unroll
    for (int mt = 0; mt < 2; mt++) {
        int r0 = bm + wm * 32 + mt * 16 + (lane >> 2);
        #pragma unroll
        for (int nt = 0; nt < 4; nt++) {
            int c0 = bn + wn * 32 + nt * 8 + (lane & 3) * 2;
            if (r0 < M)
                *(__half2*)(C + (size_t)r0 * Nn + c0) =
                    __floats2half2_rn(acc[mt][nt][0], acc[mt][nt][1]);
            if (r0 + 8 < M)
                *(__half2*)(C + (size_t)(r0 + 8) * Nn + c0) =
                    __floats2half2_rn(acc[mt][nt][2], acc[mt][nt][3]);
        }
    }
}

// ---------------- helpers ----------------
__device__ __forceinline__ float lrelu_exp(float s) {
    s = s > 0.f ? s : SLOPE * s;
    return __expf(s);
}

__device__ __forceinline__ void acc8(float* acc, float w, const uint4& v) {
    float2 f0 = __half22float2(*(__half2*)&v.x);
    float2 f1 = __half22float2(*(__half2*)&v.y);
    float2 f2 = __half22float2(*(__half2*)&v.z);
    float2 f3 = __half22float2(*(__half2*)&v.w);
    acc[0] += w * f0.x; acc[1] += w * f0.y;
    acc[2] += w * f1.x; acc[3] += w * f1.y;
    acc[4] += w * f2.x; acc[5] += w * f2.y;
    acc[6] += w * f3.x; acc[7] += w * f3.y;
}

// ---------------- aggregation layer 1: warp per node ----------------
__global__ void __launch_bounds__(256) aggregate1_kernel(const float* __restrict__ b1) {
    int n = (blockIdx.x * blockDim.x + threadIdx.x) >> 5;
    if (n >= N_NODES) return;
    int l = threadIdx.x & 31;
    int h = l >> 3;
    int r0 = g_rowptr[n], r1 = g_rowptr[n + 1];
    float dvh = g_sdst1[n * 4 + h];

    float acc[8] = {};
    float den = 0.f;
    const __half* hb = g_h1h + l * 8;

    int e = r0;
    for (; e + 3 < r1; e += 4) {
        int s0 = g_esrc[e], s1 = g_esrc[e + 1], s2 = g_esrc[e + 2], s3 = g_esrc[e + 3];
        float w0 = lrelu_exp(g_ssrc1[s0 * 4 + h] + dvh);
        float w1 = lrelu_exp(g_ssrc1[s1 * 4 + h] + dvh);
        float w2 = lrelu_exp(g_ssrc1[s2 * 4 + h] + dvh);
        float w3 = lrelu_exp(g_ssrc1[s3 * 4 + h] + dvh);
        uint4 v0 = *(const uint4*)(hb + (size_t)s0 * C1);
        uint4 v1 = *(const uint4*)(hb + (size_t)s1 * C1);
        uint4 v2 = *(const uint4*)(hb + (size_t)s2 * C1);
        uint4 v3 = *(const uint4*)(hb + (size_t)s3 * C1);
        acc8(acc, w0, v0); acc8(acc, w1, v1);
        acc8(acc, w2, v2); acc8(acc, w3, v3);
        den += (w0 + w1) + (w2 + w3);
    }
    for (; e < r1; e++) {
        int s0 = g_esrc[e];
        float w0 = lrelu_exp(g_ssrc1[s0 * 4 + h] + dvh);
        uint4 v0 = *(const uint4*)(hb + (size_t)s0 * C1);
        acc8(acc, w0, v0);
        den += w0;
    }

    float inv = 1.f / (den + 1e-16f);
    float4 bb0 = *(const float4*)(b1 + l * 8);
    float4 bb1 = *(const float4*)(b1 + l * 8 + 4);
    float o[8];
    o[0] = acc[0] * inv + bb0.x; o[1] = acc[1] * inv + bb0.y;
    o[2] = acc[2] * inv + bb0.z; o[3] = acc[3] * inv + bb0.w;
    o[4] = acc[4] * inv + bb1.x; o[5] = acc[5] * inv + bb1.y;
    o[6] = acc[6] * inv + bb1.z; o[7] = acc[7] * inv + bb1.w;
    #pragma unroll
    for (int j = 0; j < 8; j++) o[j] = o[j] > 0.f ? o[j] : expm1f(o[j]);
    __half2 p0 = __floats2half2_rn(o[0], o[1]);
    __half2 p1 = __floats2half2_rn(o[2], o[3]);
    __half2 p2 = __floats2half2_rn(o[4], o[5]);
    __half2 p3 = __floats2half2_rn(o[6], o[7]);
    uint4 u;
    u.x = *(unsigned int*)&p0; u.y = *(unsigned int*)&p1;
    u.z = *(unsigned int*)&p2; u.w = *(unsigned int*)&p3;
    *(uint4*)(g_o1h + (size_t)n * C1 + l * 8) = u;
}

// ---------------- aggregation layer 2: warp per node (fp16 out) ----------------
__global__ void __launch_bounds__(256) aggregate2_kernel(const float* __restrict__ b2) {
    int n = (blockIdx.x * blockDim.x + threadIdx.x) >> 5;
    if (n >= N_NODES) return;
    int l = threadIdx.x & 31;
    int r0 = g_rowptr[n], r1 = g_rowptr[n + 1];
    float sd = g_sdst2[n];

    float a0 = 0.f, a1 = 0.f;
    float den = 0.f;
    const __half* hb = g_h2h + l * 2;

    int e = r0;
    for (; e + 3 < r1; e += 4) {
        int s0 = g_esrc[e], s1 = g_esrc[e + 1], s2 = g_esrc[e + 2], s3 = g_esrc[e + 3];
        float w0 = lrelu_exp(g_ssrc2[s0] + sd);
        float w1 = lrelu_exp(g_ssrc2[s1] + sd);
        float w2 = lrelu_exp(g_ssrc2[s2] + sd);
        float w3 = lrelu_exp(g_ssrc2[s3] + sd);
        __half2 v0 = *(const __half2*)(hb + (size_t)s0 * HID);
        __half2 v1 = *(const __half2*)(hb + (size_t)s1 * HID);
        __half2 v2 = *(const __half2*)(hb + (size_t)s2 * HID);
        __half2 v3 = *(const __half2*)(hb + (size_t)s3 * HID);
        float2 f0 = __half22float2(v0), f1 = __half22float2(v1);
        float2 f2 = __half22float2(v2), f3 = __half22float2(v3);
        a0 += w0 * f0.x + w1 * f1.x + w2 * f2.x + w3 * f3.x;
        a1 += w0 * f0.y + w1 * f1.y + w2 * f2.y + w3 * f3.y;
        den += (w0 + w1) + (w2 + w3);
    }
    for (; e < r1; e++) {
        int s0 = g_esrc[e];
        float w0 = lrelu_exp(g_ssrc2[s0] + sd);
        float2 f0 = __half22float2(*(const __half2*)(hb + (size_t)s0 * HID));
        a0 += w0 * f0.x; a1 += w0 * f0.y;
        den += w0;
    }

    float inv = 1.f / (den + 1e-16f);
    float o0 = a0 * inv + b2[l * 2];
    float o1 = a1 * inv + b2[l * 2 + 1];
    o0 = o0 > 0.f ? o0 : expm1f(o0);
    o1 = o1 > 0.f ? o1 : expm1f(o1);
    *(__half2*)(g_o2h + (size_t)n * HID + l * 2) = __floats2half2_rn(o0, o1);
}

// ---------------- graph offsets ----------------
__global__ void graph_offsets_kernel(const int* __restrict__ batch) {
    int g = blockIdx.x * blockDim.x + threadIdx.x;
    if (g > NG) return;
    if (g == NG) { g_goff[NG] = N_NODES; return; }
    int lo = 0, hi = N_NODES;
    while (lo < hi) {
        int mid = (lo + hi) >> 1;
        if (batch[mid] < g) lo = mid + 1; else hi = mid;
    }
    g_goff[g] = lo;
}

// ---------------- pool + fc + log_softmax (fp16 in) ----------------
__global__ void __launch_bounds__(256) pool_fc_kernel(const float* __restrict__ fcw,
                                                      const float* __restrict__ fcb,
                                                      float* __restrict__ out) {
    int g = blockIdx.x;
    int t = threadIdx.x;
    int c2 = t & 31, rep = t >> 5;   // 32 channel-pairs x 8 reps
    int s = g_goff[g], e = g_goff[g + 1];
    float sx = 0.f, sy = 0.f;
    for (int i = s + rep; i < e; i += 8) {
        float2 f = __half22float2(*(const __half2*)(g_o2h + (size_t)i * HID + c2 * 2));
        sx += f.x; sy += f.y;
    }
    __shared__ float2 red[256];
    red[t] = make_float2(sx, sy);
    __syncthreads();
    if (t < 32) {
        float2 tot = make_float2(0.f, 0.f);
        #pragma unroll
        for (int r = 0; r < 8; r++) {
            float2 v = red[r * 32 + t];
            tot.x += v.x; tot.y += v.y;
        }
        float cnt = (float)max(e - s, 1);
        red[t] = make_float2(tot.x / cnt, tot.y / cnt);
    }
    __syncthreads();
    if (t < 2) {
        float l = fcb[t];
        for (int c = 0; c < 32; c++) {
            float2 p = red[c];
            l += p.x * fcw[(c * 2) * 2 + t] + p.y * fcw[(c * 2 + 1) * 2 + t];
        }
        red[64 + t].x = l;
    }
    __syncthreads();
    if (t == 0) {
        float l0 = red[64].x, l1 = red[65].x;
        float m = fmaxf(l0, l1);
        float lse = m + logf(__expf(l0 - m) + __expf(l1 - m));
        out[g * 2 + 0] = l0 - lse;
        out[g * 2 + 1] = l1 - lse;
    }
}

// ---------------- launch ----------------
extern "C" void kernel_launch(void* const* d_in, const int* in_sizes, int n_in,
                              void* d_out, int out_size) {
    const float* x    = (const float*)d_in[0];
    const int*   ei   = (const int*)d_in[1];
    const int*   bat  = (const int*)d_in[2];
    const float* W1   = (const float*)d_in[3];
    const float* as1  = (const float*)d_in[4];
    const float* ad1  = (const float*)d_in[5];
    const float* b1   = (const float*)d_in[6];
    const float* W2   = (const float*)d_in[7];
    const float* as2  = (const float*)d_in[8];
    const float* ad2  = (const float*)d_in[9];
    const float* b2   = (const float*)d_in[10];
    const float* fcw  = (const float*)d_in[11];
    const float* fcb  = (const float*)d_in[12];
    float* out = (float*)d_out;

    __half* w1hp; cudaGetSymbolAddress((void**)&w1hp, g_W1h);
    __half* w2hp; cudaGetSymbolAddress((void**)&w2hp, g_W2h);
    __half* h1p;  cudaGetSymbolAddress((void**)&h1p,  g_h1h);
    __half* o1p;  cudaGetSymbolAddress((void**)&o1p,  g_o1h);
    __half* h2p;  cudaGetSymbolAddress((void**)&h2p,  g_h2h);
    float* s1p;   cudaGetSymbolAddress((void**)&s1p,  g_ssrc1);
    float* d1p;   cudaGetSymbolAddress((void**)&d1p,  g_sdst1);
    float* s2p;   cudaGetSymbolAddress((void**)&s2p,  g_ssrc2);
    float* d2p;   cudaGetSymbolAddress((void**)&d2p,  g_sdst2);
    int* degp;    cudaGetSymbolAddress((void**)&degp, g_deg);
    int* curp;    cudaGetSymbolAddress((void**)&curp, g_cursor);

    // side stream + events for fork/join inside graph capture
    cudaStream_t side;
    cudaStreamCreateWithFlags(&side, cudaStreamNonBlocking);
    cudaEvent_t evF, evJ;
    cudaEventCreateWithFlags(&evF, cudaEventDisableTiming);
    cudaEventCreateWithFlags(&evJ, cudaEventDisableTiming);

    // fork: CSR build on side stream
    cudaEventRecord(evF, 0);
    cudaStreamWaitEvent(side, evF, 0);
    cudaMemsetAsync(degp, 0, N_NODES * sizeof(int), side);
    cudaMemsetAsync(curp, 0, N_NODES * sizeof(int), side);
    hist_kernel<<<(N_EDGES + 255) / 256, 256, 0, side>>>(ei);
    scan_kernel<<<1, 1024, 0, side>>>();
    scatter_kernel<<<(N_EDGES + 255) / 256, 256, 0, side>>>(ei);
    cudaEventRecord(evJ, side);

    // main: weight converts (one launch) + graph offsets + gemm1 (scores fused)
    int nW = F_IN * C1 + C1 * HID;
    f2h2_kernel<<<(nW / 4 + 255) / 256, 256>>>(W1, w1hp, F_IN * C1, W2, w2hp, C1 * HID);
    graph_offsets_kernel<<<1, 128>>>(bat);

    dim3 g1(C1 / 64, (N_NODES + 127) / 128);
    gemm_gat_kernel<true><<<g1, 256>>>(x, w1hp, h1p, N_NODES, C1, F_IN,
                                       as1, ad1, s1p, d1p, HEADS);

    // join: aggregate1 needs CSR + scores
    cudaStreamWaitEvent(0, evJ, 0);
    aggregate1_kernel<<<(N_NODES * 32 + 255) / 256, 256>>>(b1);

    // layer 2 (scores fused)
    dim3 g2(HID / 64, (N_NODES + 127) / 128);
    gemm_gat_kernel<false><<<g2, 256>>>(o1p, w2hp, h2p, N_NODES, HID, C1,
                                        as2, ad2, s2p, d2p, 1);
    aggregate2_kernel<<<(N_NODES * 32 + 255) / 256, 256>>>(b2);

    // pool + classifier
    pool_fc_kernel<<<NG, 256>>>(fcw, fcb, out);
}